// round 2
// baseline (speedup 1.0000x reference)
#include <cuda_runtime.h>

#define NPTS  50000
#define NEDGE 800000
#define HID   64
#define INC   16
#define OUTC  16

// Scratch: G[n][o][j] (o-major, j contiguous for float4 reads) and cb[n][o]
__device__ float g_G[(size_t)NPTS * 1024];
__device__ float g_cb[NPTS * OUTC];
__device__ int   g_is64;

__device__ __forceinline__ float gelu_exact(float v) {
    return 0.5f * v * (1.0f + erff(v * 0.70710678118654752440f));
}

__global__ void zero_out_kernel(float* out, int n) {
    int i = blockIdx.x * blockDim.x + threadIdx.x;
    if (i < n) out[i] = 0.0f;
}

// Detect whether edge_index buffer is int64 (odd 32-bit words all zero) or int32.
__global__ void detect_dtype_kernel(const int* __restrict__ ei32) {
    int all_zero = 1;
    for (int k = 0; k < 64; k++)
        if (ei32[2 * k + 1] != 0) { all_zero = 0; break; }
    g_is64 = all_zero;
}

// G[n, o*64+j] = sum_i Wo[j*256 + i*16 + o] * x[n*16+i]
__global__ __launch_bounds__(256) void precompute_G(
    const float* __restrict__ x, const float* __restrict__ Wo)
{
    __shared__ float sx[16 * 16];          // 16 nodes x 16 channels
    int base = blockIdx.x * 16;
    int tid = threadIdx.x;
    sx[tid] = x[base * 16 + tid];
    __syncthreads();

    for (int c = tid; c < 1024; c += 256) {
        int o = c >> 6, j = c & 63;
        float a[16];
        #pragma unroll
        for (int i = 0; i < 16; i++)
            a[i] = __ldg(&Wo[j * 256 + i * 16 + o]);   // 64KB, L1/L2-resident
        #pragma unroll 4
        for (int n = 0; n < 16; n++) {
            const float* xp = sx + n * 16;
            float acc = 0.0f;
            #pragma unroll
            for (int i = 0; i < 16; i++) acc += a[i] * xp[i];
            g_G[(size_t)(base + n) * 1024 + c] = acc;
        }
    }
}

// cb[n,o] = sum_i bo[i*16+o] * x[n*16+i]
__global__ void precompute_cb(const float* __restrict__ x, const float* __restrict__ bo) {
    int t = blockIdx.x * blockDim.x + threadIdx.x;
    if (t >= NPTS * OUTC) return;
    int n = t >> 4, o = t & 15;
    float acc = 0.0f;
    #pragma unroll
    for (int i = 0; i < 16; i++) acc += bo[i * 16 + o] * x[n * 16 + i];
    g_cb[t] = acc;
}

// One warp per edge (grid-strided). h1/h2 live warp-distributed in registers;
// broadcasts via shfl.idx. Layer 3 reads precomputed G[src].
__global__ __launch_bounds__(256) void edge_kernel(
    const float* __restrict__ pos, const int* __restrict__ ei,
    const float* __restrict__ W1, const float* __restrict__ b1,
    const float* __restrict__ Wh, const float* __restrict__ bh,
    float* __restrict__ out)
{
    __shared__ float sW1[6 * 64];
    __shared__ float sb1[64];
    __shared__ float sbh[64];
    __shared__ float sWh[64 * 64];

    int tid = threadIdx.x;
    for (int t = tid; t < 6 * 64; t += 256) sW1[t] = W1[t];
    if (tid < 64) { sb1[tid] = b1[tid]; sbh[tid] = bh[tid]; }
    for (int t = tid; t < 64 * 64; t += 256) sWh[t] = Wh[t];
    __syncthreads();

    const int is64 = g_is64;   // uniform across grid
    const unsigned F = 0xffffffffu;
    int lane = tid & 31;
    int gw = (blockIdx.x * 256 + tid) >> 5;       // global warp id
    int nw = (gridDim.x * 256) >> 5;              // total warps
    int c0 = lane, c1 = lane + 32;
    int o = lane & 15, half = lane >> 4;

    for (int e = gw; e < NEDGE; e += nw) {
        int src, dst;
        if (is64) {
            src = ei[2 * e];                       // low word of int64
            dst = ei[2 * NEDGE + 2 * e];
        } else {
            src = ei[e];
            dst = ei[NEDGE + e];
        }

        float p0 = pos[src * 3 + 0], p1 = pos[src * 3 + 1], p2 = pos[src * 3 + 2];
        float p3 = pos[dst * 3 + 0], p4 = pos[dst * 3 + 1], p5 = pos[dst * 3 + 2];

        // ---- layer 1: h1 = gelu(pe @ W1 + b1), channels (lane, lane+32) ----
        float a0 = sb1[c0];
        float a1 = sb1[c1];
        a0 += p0 * sW1[0 * 64 + c0]; a1 += p0 * sW1[0 * 64 + c1];
        a0 += p1 * sW1[1 * 64 + c0]; a1 += p1 * sW1[1 * 64 + c1];
        a0 += p2 * sW1[2 * 64 + c0]; a1 += p2 * sW1[2 * 64 + c1];
        a0 += p3 * sW1[3 * 64 + c0]; a1 += p3 * sW1[3 * 64 + c1];
        a0 += p4 * sW1[4 * 64 + c0]; a1 += p4 * sW1[4 * 64 + c1];
        a0 += p5 * sW1[5 * 64 + c0]; a1 += p5 * sW1[5 * 64 + c1];
        float h1a = gelu_exact(a0);
        float h1b = gelu_exact(a1);

        // ---- layer 2: h2 = gelu(h1 @ Wh + bh) ----
        float b0 = sbh[c0];
        float b1v = sbh[c1];
        #pragma unroll 8
        for (int j = 0; j < 32; j++) {
            float hj = __shfl_sync(F, h1a, j);
            b0  += hj * sWh[j * 64 + c0];
            b1v += hj * sWh[j * 64 + c1];
        }
        #pragma unroll 8
        for (int j = 0; j < 32; j++) {
            float hj = __shfl_sync(F, h1b, j);
            b0  += hj * sWh[(j + 32) * 64 + c0];
            b1v += hj * sWh[(j + 32) * 64 + c1];
        }
        float h2a = gelu_exact(b0);
        float h2b = gelu_exact(b1v);

        // ---- redistribute h2 so lane L holds (h2[2L], h2[2L+1]) ----
        int sl = (2 * lane) & 31;
        float pa  = __shfl_sync(F, h2a, sl);
        float pb  = __shfl_sync(F, h2b, sl);
        float q0 = (lane < 16) ? pa : pb;        // h2[2*lane]
        float pa2 = __shfl_sync(F, h2a, sl + 1);
        float pb2 = __shfl_sync(F, h2b, sl + 1);
        float q1 = (lane < 16) ? pa2 : pb2;      // h2[2*lane+1]

        // ---- layer 3: m_partial(o, half) = sum_{j in half} h2[j]*G[src,o,j] ----
        const float4* gp = (const float4*)(g_G + (size_t)src * 1024 + (o * 64 + half * 32));
        float m = 0.0f;
        #pragma unroll
        for (int k = 0; k < 8; k++) {
            float4 g = __ldg(gp + k);
            int sb = half * 16 + k * 2;              // src lane for this 4-group
            float u0 = __shfl_sync(F, q0, sb);       // j = half*32 + 4k
            float u1 = __shfl_sync(F, q1, sb);       // j = half*32 + 4k+1
            float u2 = __shfl_sync(F, q0, sb + 1);   // j = half*32 + 4k+2
            float u3 = __shfl_sync(F, q1, sb + 1);   // j = half*32 + 4k+3
            m += g.x * u0 + g.y * u1 + g.z * u2 + g.w * u3;
        }
        m += __shfl_down_sync(F, m, 16);         // combine the two j-halves

        if (lane < 16)
            atomicAdd(out + dst * 16 + o, m + __ldg(&g_cb[src * 16 + o]));
    }
}

extern "C" void kernel_launch(void* const* d_in, const int* in_sizes, int n_in,
                              void* d_out, int out_size) {
    const float* x   = (const float*)d_in[0];
    const float* pos = (const float*)d_in[1];
    const int*   ei  = (const int*)d_in[2];
    const float* W1  = (const float*)d_in[3];
    const float* b1  = (const float*)d_in[4];
    const float* Wh  = (const float*)d_in[5];
    const float* bh  = (const float*)d_in[6];
    const float* Wo  = (const float*)d_in[7];
    const float* bo  = (const float*)d_in[8];
    float* out = (float*)d_out;

    detect_dtype_kernel<<<1, 1>>>(ei);
    zero_out_kernel<<<(NPTS * OUTC + 255) / 256, 256>>>(out, NPTS * OUTC);
    precompute_G<<<NPTS / 16, 256>>>(x, Wo);
    precompute_cb<<<(NPTS * OUTC + 255) / 256, 256>>>(x, bo);
    edge_kernel<<<148 * 6, 256>>>(pos, ei, W1, b1, Wh, bh, out);
}